// round 3
// baseline (speedup 1.0000x reference)
#include <cuda_runtime.h>
#include <math.h>
#include <stdint.h>

// ---------------- problem constants ----------------
#define S_LEN 4096
#define HID   2048
#define NH    8
#define NVH   16
#define DK    128
#define DV    128
#define KEY_DIM  (NH*DK)    // 1024
#define VAL_DIM  (NVH*DV)   // 2048
#define CONV  4
#define EPS_  1e-6f
#define SCALE_ 0.08838834764831845f   // 128^-0.5

// ---------------- workspace (device globals; no allocation allowed) -------
static constexpr size_t SZ_QPRE = (size_t)S_LEN * KEY_DIM;   // 4194304
static constexpr size_t SZ_VPRE = (size_t)S_LEN * VAL_DIM;   // 8388608
static constexpr size_t SZ_AB   = (size_t)S_LEN * NVH;       // 65536

static constexpr size_t OF_QPRE = 0;
static constexpr size_t OF_KPRE = OF_QPRE + SZ_QPRE;
static constexpr size_t OF_VPRE = OF_KPRE + SZ_QPRE;
static constexpr size_t OF_GATE = OF_VPRE + SZ_VPRE;
static constexpr size_t OF_APRE = OF_GATE + SZ_VPRE;
static constexpr size_t OF_BPRE = OF_APRE + SZ_AB;
static constexpr size_t OF_QN   = OF_BPRE + SZ_AB;
static constexpr size_t OF_KN   = OF_QN + SZ_QPRE;
static constexpr size_t OF_VN   = OF_KN + SZ_QPRE;
static constexpr size_t OF_DB   = OF_VN + SZ_VPRE;           // float2 per (t,h)
static constexpr size_t OF_O    = OF_DB + 2*SZ_AB;
static constexpr size_t OF_OG   = OF_O + SZ_VPRE;
static constexpr size_t WS_TOTAL = OF_OG + SZ_VPRE;          // ~59M floats

__device__ float g_ws_gdn[WS_TOTAL];

// ---------------- GEMM: C[M,N] = A[M,K] * B[N,K]^T (all row-major fp32) ---
#define BM 128
#define BN 128
#define BKK 8
#define TM 8
#define TN 8

__global__ __launch_bounds__(256) void gemm_nt(
    const float* __restrict__ A, const float* __restrict__ B,
    float* __restrict__ C, int M, int N, int K)
{
    __shared__ float As[BKK][BM];
    __shared__ float Bs[BKK][BN];
    int tid = threadIdx.x;
    int tx = tid & 15, ty = tid >> 4;
    int m0 = blockIdx.y * BM, n0 = blockIdx.x * BN;

    int lrow = tid >> 1;          // 0..127
    int lcol = (tid & 1) * 4;     // 0 or 4
    const float* Ag = A + (size_t)(m0 + lrow) * K + lcol;
    const float* Bg = B + (size_t)(n0 + lrow) * K + lcol;
    bool bvalid = (n0 + lrow) < N;

    float acc[TM][TN];
#pragma unroll
    for (int i = 0; i < TM; i++)
#pragma unroll
        for (int j = 0; j < TN; j++) acc[i][j] = 0.f;

    for (int kb = 0; kb < K; kb += BKK) {
        float4 a4 = *(const float4*)(Ag + kb);
        float4 b4 = make_float4(0.f,0.f,0.f,0.f);
        if (bvalid) b4 = *(const float4*)(Bg + kb);
        As[lcol+0][lrow] = a4.x; As[lcol+1][lrow] = a4.y;
        As[lcol+2][lrow] = a4.z; As[lcol+3][lrow] = a4.w;
        Bs[lcol+0][lrow] = b4.x; Bs[lcol+1][lrow] = b4.y;
        Bs[lcol+2][lrow] = b4.z; Bs[lcol+3][lrow] = b4.w;
        __syncthreads();
#pragma unroll
        for (int kk = 0; kk < BKK; kk++) {
            float ar[TM], br[TN];
            *(float4*)&ar[0] = *(const float4*)&As[kk][ty*TM];
            *(float4*)&ar[4] = *(const float4*)&As[kk][ty*TM+4];
            *(float4*)&br[0] = *(const float4*)&Bs[kk][tx*TN];
            *(float4*)&br[4] = *(const float4*)&Bs[kk][tx*TN+4];
#pragma unroll
            for (int i = 0; i < TM; i++)
#pragma unroll
                for (int j = 0; j < TN; j++)
                    acc[i][j] = fmaf(ar[i], br[j], acc[i][j]);
        }
        __syncthreads();
    }
#pragma unroll
    for (int i = 0; i < TM; i++) {
        int m = m0 + ty*TM + i;
#pragma unroll
        for (int j = 0; j < TN; j += 4) {
            int n = n0 + tx*TN + j;
            if (n + 3 < N) {
                float4 v = make_float4(acc[i][j], acc[i][j+1], acc[i][j+2], acc[i][j+3]);
                *(float4*)&C[(size_t)m * N + n] = v;
            }
        }
    }
}

// ---------------- conv + silu + l2norm for q/k ----------------------------
__global__ __launch_bounds__(128) void convqk_kernel(
    const float* __restrict__ pre, const float* __restrict__ cw,
    float* __restrict__ out, float scale)
{
    int t = blockIdx.x >> 3;
    int h = blockIdx.x & 7;
    int c = threadIdx.x;
    int ch = h * DK + c;
    float y = 0.f;
#pragma unroll
    for (int j = 0; j < CONV; j++) {
        int tt = t - (CONV-1) + j;
        float xv = (tt >= 0) ? pre[(size_t)tt * KEY_DIM + ch] : 0.f;
        y = fmaf(xv, cw[ch*CONV + j], y);
    }
    y = y / (1.f + expf(-y));          // silu
    float ss = y * y;
#pragma unroll
    for (int off = 16; off; off >>= 1) ss += __shfl_xor_sync(0xffffffffu, ss, off);
    __shared__ float wss[4];
    if ((threadIdx.x & 31) == 0) wss[threadIdx.x >> 5] = ss;
    __syncthreads();
    float tot = wss[0] + wss[1] + wss[2] + wss[3];
    out[(size_t)t * KEY_DIM + ch] = y * rsqrtf(tot + EPS_) * scale;
}

// ---------------- conv + silu for v ---------------------------------------
__global__ __launch_bounds__(256) void convv_kernel(
    const float* __restrict__ pre, const float* __restrict__ cw,
    float* __restrict__ out)
{
    int idx = blockIdx.x * blockDim.x + threadIdx.x;
    int t = idx >> 11;
    int ch = idx & 2047;
    float y = 0.f;
#pragma unroll
    for (int j = 0; j < CONV; j++) {
        int tt = t - (CONV-1) + j;
        float xv = (tt >= 0) ? pre[(size_t)tt * VAL_DIM + ch] : 0.f;
        y = fmaf(xv, cw[ch*CONV + j], y);
    }
    out[idx] = y / (1.f + expf(-y));
}

// ---------------- decay / beta --------------------------------------------
__global__ __launch_bounds__(256) void db_kernel(
    const float* __restrict__ apre, const float* __restrict__ bpre,
    const float* __restrict__ A_log, const float* __restrict__ dt_bias,
    float2* __restrict__ db)
{
    int idx = blockIdx.x * blockDim.x + threadIdx.x;
    if (idx >= S_LEN * NVH) return;
    int h = idx & (NVH - 1);
    float a = apre[idx] + dt_bias[h];
    float sp = (a > 20.f) ? a : log1pf(expf(a));
    float g = -expf(A_log[h]) * sp;
    float decay = expf(g);
    float beta = 1.f / (1.f + expf(-bpre[idx]));
    db[idx] = make_float2(decay, beta);
}

// ---------------- sequential delta-rule scan ------------------------------
// 2048 independent column recurrences: 8 lanes per column, 16 state elems/lane.
// Grid: 32 blocks (16 value heads x 2), 512 threads (16 warps x 4 columns).
// GVA: value head h reads key/query head h/2.
__global__ __launch_bounds__(512) void scan_kernel(
    const float* __restrict__ k, const float* __restrict__ q,
    const float* __restrict__ v, const float2* __restrict__ db,
    float* __restrict__ o)
{
    int h = blockIdx.x >> 1;          // value head 0..15
    int hk = h >> 1;                  // key/query head 0..7 (GVA=2)
    int warp = threadIdx.x >> 5;
    int lane = threadIdx.x & 31;
    int g = lane >> 3;
    int s = lane & 7;
    int col = (blockIdx.x & 1) * 64 + warp * 4 + g;

    const float* kb = k + hk * DK + s * 16;  // stride KEY_DIM per t
    const float* qb = q + hk * DK + s * 16;
    const float* vb = v + h * DV + col;      // stride VAL_DIM per t
    const float2* dbb = db + h;              // stride NVH per t
    float* ob = o + h * DV + col;

    float S[16];
#pragma unroll
    for (int i = 0; i < 16; i++) S[i] = 0.f;

    float kc[16], qc[16], vc; float2 dc;
#pragma unroll
    for (int i = 0; i < 16; i += 4) {
        *(float4*)&kc[i] = *(const float4*)(kb + i);
        *(float4*)&qc[i] = *(const float4*)(qb + i);
    }
    vc = *vb; dc = *dbb;

#pragma unroll 2
    for (int t = 0; t < S_LEN; t++) {
        int tn = (t + 1 < S_LEN) ? t + 1 : t;
        float kn[16], qn[16], vn; float2 dn;
        const float* kpt = kb + (size_t)tn * KEY_DIM;
        const float* qpt = qb + (size_t)tn * KEY_DIM;
#pragma unroll
        for (int i = 0; i < 16; i += 4) {
            *(float4*)&kn[i] = *(const float4*)(kpt + i);
            *(float4*)&qn[i] = *(const float4*)(qpt + i);
        }
        vn = vb[(size_t)tn * VAL_DIM];
        dn = dbb[(size_t)tn * NVH];

        // pred = k . (decay*S_old) = decay * (k . S_old)
        float a0 = 0.f, a1 = 0.f, a2 = 0.f, a3 = 0.f;
#pragma unroll
        for (int i = 0; i < 16; i += 4) {
            a0 = fmaf(kc[i],   S[i],   a0);
            a1 = fmaf(kc[i+1], S[i+1], a1);
            a2 = fmaf(kc[i+2], S[i+2], a2);
            a3 = fmaf(kc[i+3], S[i+3], a3);
        }
        float p = (a0 + a1) + (a2 + a3);
        p += __shfl_xor_sync(0xffffffffu, p, 1);
        p += __shfl_xor_sync(0xffffffffu, p, 2);
        p += __shfl_xor_sync(0xffffffffu, p, 4);
        float delta = (vc - p * dc.x) * dc.y;

        // S = decay*S + k*delta ; o = q . S_new
        float b0 = 0.f, b1 = 0.f, b2 = 0.f, b3 = 0.f;
#pragma unroll
        for (int i = 0; i < 16; i += 4) {
            S[i]   = fmaf(S[i],   dc.x, kc[i]   * delta);
            S[i+1] = fmaf(S[i+1], dc.x, kc[i+1] * delta);
            S[i+2] = fmaf(S[i+2], dc.x, kc[i+2] * delta);
            S[i+3] = fmaf(S[i+3], dc.x, kc[i+3] * delta);
            b0 = fmaf(qc[i],   S[i],   b0);
            b1 = fmaf(qc[i+1], S[i+1], b1);
            b2 = fmaf(qc[i+2], S[i+2], b2);
            b3 = fmaf(qc[i+3], S[i+3], b3);
        }
        float ov = (b0 + b1) + (b2 + b3);
        ov += __shfl_xor_sync(0xffffffffu, ov, 1);
        ov += __shfl_xor_sync(0xffffffffu, ov, 2);
        ov += __shfl_xor_sync(0xffffffffu, ov, 4);
        if (s == 0) ob[(size_t)t * VAL_DIM] = ov;

#pragma unroll
        for (int i = 0; i < 16; i++) { kc[i] = kn[i]; qc[i] = qn[i]; }
        vc = vn; dc = dn;
    }
}

// ---------------- gated RMS norm ------------------------------------------
__global__ __launch_bounds__(128) void gnorm_kernel(
    const float* __restrict__ o, const float* __restrict__ gate,
    const float* __restrict__ w_norm, float* __restrict__ og)
{
    int t = blockIdx.x >> 4;
    int h = blockIdx.x & 15;
    int c = threadIdx.x;
    size_t idx = (size_t)t * VAL_DIM + h * DV + c;
    float gt = gate[idx];
    float y = o[idx] * (gt / (1.f + expf(-gt)));
    float ss = y * y;
#pragma unroll
    for (int off = 16; off; off >>= 1) ss += __shfl_xor_sync(0xffffffffu, ss, off);
    __shared__ float wss[4];
    if ((threadIdx.x & 31) == 0) wss[threadIdx.x >> 5] = ss;
    __syncthreads();
    float mean = (wss[0] + wss[1] + wss[2] + wss[3]) * (1.f / DV);
    og[idx] = y * rsqrtf(mean + EPS_) * w_norm[c];
}

// ---------------- launch ---------------------------------------------------
extern "C" void kernel_launch(void* const* d_in, const int* in_sizes, int n_in,
                              void* d_out, int out_size)
{
    const float* x      = (const float*)d_in[0];
    const float* Wq     = (const float*)d_in[1];
    const float* Wk     = (const float*)d_in[2];
    const float* Wv     = (const float*)d_in[3];
    const float* Wa     = (const float*)d_in[4];
    const float* Wb     = (const float*)d_in[5];
    const float* Wg     = (const float*)d_in[6];
    const float* Wo     = (const float*)d_in[7];
    const float* conv_q = (const float*)d_in[8];
    const float* conv_k = (const float*)d_in[9];
    const float* conv_v = (const float*)d_in[10];
    const float* A_log  = (const float*)d_in[11];
    const float* dt_b   = (const float*)d_in[12];
    const float* w_norm = (const float*)d_in[13];

    void* wsp = nullptr;
    cudaGetSymbolAddress(&wsp, g_ws_gdn);
    float* ws = (float*)wsp;
    float* qpre = ws + OF_QPRE;
    float* kpre = ws + OF_KPRE;
    float* vpre = ws + OF_VPRE;
    float* gate = ws + OF_GATE;
    float* apre = ws + OF_APRE;
    float* bpre = ws + OF_BPRE;
    float* qn   = ws + OF_QN;
    float* kn   = ws + OF_KN;
    float* vn   = ws + OF_VN;
    float2* db  = (float2*)(ws + OF_DB);
    float* o    = ws + OF_O;
    float* og   = ws + OF_OG;
    float* out  = (float*)d_out;

    dim3 blk(256);
    dim3 g_qk((KEY_DIM + BN - 1) / BN, (S_LEN + BM - 1) / BM);   // (8,32)
    dim3 g_v ((VAL_DIM + BN - 1) / BN, (S_LEN + BM - 1) / BM);   // (16,32)
    dim3 g_ab((NVH + BN - 1) / BN,     (S_LEN + BM - 1) / BM);   // (1,32)

    gemm_nt<<<g_qk, blk>>>(x, Wq, qpre, S_LEN, KEY_DIM, HID);
    gemm_nt<<<g_qk, blk>>>(x, Wk, kpre, S_LEN, KEY_DIM, HID);
    gemm_nt<<<g_v,  blk>>>(x, Wv, vpre, S_LEN, VAL_DIM, HID);
    gemm_nt<<<g_v,  blk>>>(x, Wg, gate, S_LEN, VAL_DIM, HID);
    gemm_nt<<<g_ab, blk>>>(x, Wa, apre, S_LEN, NVH, HID);
    gemm_nt<<<g_ab, blk>>>(x, Wb, bpre, S_LEN, NVH, HID);

    convqk_kernel<<<S_LEN * NH, 128>>>(qpre, conv_q, qn, SCALE_);
    convqk_kernel<<<S_LEN * NH, 128>>>(kpre, conv_k, kn, 1.f);
    convv_kernel<<<(S_LEN * VAL_DIM) / 256, 256>>>(vpre, conv_v, vn);
    db_kernel<<<(S_LEN * NVH + 255) / 256, 256>>>(apre, bpre, A_log, dt_b, db);

    scan_kernel<<<32, 512>>>(kn, qn, vn, db, o);

    gnorm_kernel<<<S_LEN * NVH, 128>>>(o, gate, w_norm, og);

    gemm_nt<<<g_v, blk>>>(og, Wo, out, S_LEN, HID, VAL_DIM);
}

// round 4
// speedup vs baseline: 1.3691x; 1.3691x over previous
#include <cuda_runtime.h>
#include <math.h>
#include <stdint.h>

// ---------------- problem constants ----------------
#define S_LEN 4096
#define HID   2048
#define NH    8
#define NVH   16
#define DK    128
#define DV    128
#define KEY_DIM  (NH*DK)    // 1024
#define VAL_DIM  (NVH*DV)   // 2048
#define CONV  4
#define EPS_  1e-6f
#define SCALE_ 0.08838834764831845f   // 128^-0.5

// ---------------- workspace (device globals; no allocation allowed) -------
static constexpr size_t SZ_QPRE = (size_t)S_LEN * KEY_DIM;
static constexpr size_t SZ_VPRE = (size_t)S_LEN * VAL_DIM;
static constexpr size_t SZ_AB   = (size_t)S_LEN * NVH;

static constexpr size_t OF_QPRE = 0;
static constexpr size_t OF_KPRE = OF_QPRE + SZ_QPRE;
static constexpr size_t OF_VPRE = OF_KPRE + SZ_QPRE;
static constexpr size_t OF_GATE = OF_VPRE + SZ_VPRE;
static constexpr size_t OF_APRE = OF_GATE + SZ_VPRE;
static constexpr size_t OF_BPRE = OF_APRE + SZ_AB;
static constexpr size_t OF_QN   = OF_BPRE + SZ_AB;
static constexpr size_t OF_KN   = OF_QN + SZ_QPRE;
static constexpr size_t OF_VN   = OF_KN + SZ_QPRE;
static constexpr size_t OF_DB   = OF_VN + SZ_VPRE;           // float2 per (t,h)
static constexpr size_t OF_O    = OF_DB + 2*SZ_AB;
static constexpr size_t OF_OG   = OF_O + SZ_VPRE;
static constexpr size_t WS_TOTAL = OF_OG + SZ_VPRE;

__device__ float g_ws_gdn[WS_TOTAL];

// ================= tf32 tensor-core GEMM ==================================
// C[M,N] = A[M,K] * B[N,K]^T, fp32 in/out, tf32 mma.sync compute.
// Requires M%128==0, N%128==0, K%16==0 (true for all big GEMMs here).
#define GBM 128
#define GBN 128
#define GBK 16

__device__ __forceinline__ uint32_t f2tf32(float x) {
    uint32_t r;
    asm("cvt.rna.tf32.f32 %0, %1;" : "=r"(r) : "f"(x));
    return r;
}

__device__ __forceinline__ void mma_tf32(float* c, const uint32_t* a, const uint32_t* b) {
    asm volatile(
        "mma.sync.aligned.m16n8k8.row.col.f32.tf32.tf32.f32 "
        "{%0,%1,%2,%3}, {%4,%5,%6,%7}, {%8,%9}, {%0,%1,%2,%3};"
        : "+f"(c[0]), "+f"(c[1]), "+f"(c[2]), "+f"(c[3])
        : "r"(a[0]), "r"(a[1]), "r"(a[2]), "r"(a[3]), "r"(b[0]), "r"(b[1]));
}

__global__ __launch_bounds__(256) void gemm_tf32(
    const float* __restrict__ A, const float* __restrict__ B,
    float* __restrict__ C, int M, int N, int K)
{
    __shared__ uint32_t As[2][GBM][GBK + 4];
    __shared__ uint32_t Bs[2][GBN][GBK + 4];

    int tid = threadIdx.x;
    int warp = tid >> 5;
    int lane = tid & 31;
    int gid = lane >> 2;      // group id 0..7
    int tig = lane & 3;       // thread in group 0..3

    int m0 = blockIdx.y * GBM;
    int n0 = blockIdx.x * GBN;
    int wm = (warp >> 2) * 64;   // warp m offset within block tile
    int wn = (warp & 3) * 32;    // warp n offset

    // global load mapping: each thread loads 8 consecutive floats of one row
    int lrow = tid >> 1;             // 0..127
    int lk   = (tid & 1) * 8;        // 0 or 8
    const float* Ag = A + (size_t)(m0 + lrow) * K + lk;
    const float* Bg = B + (size_t)(n0 + lrow) * K + lk;

    float acc[4][4][4];
#pragma unroll
    for (int i = 0; i < 4; i++)
#pragma unroll
        for (int j = 0; j < 4; j++)
#pragma unroll
            for (int r = 0; r < 4; r++) acc[i][j][r] = 0.f;

    int kIters = K / GBK;

    // preload iter 0
    float4 a0 = *(const float4*)(Ag);
    float4 a1 = *(const float4*)(Ag + 4);
    float4 b0 = *(const float4*)(Bg);
    float4 b1 = *(const float4*)(Bg + 4);
    {
        uint4* da = (uint4*)&As[0][lrow][lk];
        uint4* db_ = (uint4*)&Bs[0][lrow][lk];
        da[0] = make_uint4(f2tf32(a0.x), f2tf32(a0.y), f2tf32(a0.z), f2tf32(a0.w));
        da[1] = make_uint4(f2tf32(a1.x), f2tf32(a1.y), f2tf32(a1.z), f2tf32(a1.w));
        db_[0] = make_uint4(f2tf32(b0.x), f2tf32(b0.y), f2tf32(b0.z), f2tf32(b0.w));
        db_[1] = make_uint4(f2tf32(b1.x), f2tf32(b1.y), f2tf32(b1.z), f2tf32(b1.w));
    }
    __syncthreads();

    int buf = 0;
    for (int it = 0; it < kIters; it++) {
        bool more = (it + 1) < kIters;
        if (more) {
            const float* Agn = Ag + (size_t)(it + 1) * GBK;
            const float* Bgn = Bg + (size_t)(it + 1) * GBK;
            a0 = *(const float4*)(Agn);
            a1 = *(const float4*)(Agn + 4);
            b0 = *(const float4*)(Bgn);
            b1 = *(const float4*)(Bgn + 4);
        }

        // compute on buf: two k8 steps
#pragma unroll
        for (int s = 0; s < 2; s++) {
            int k8 = s * 8;
            uint32_t af[4][4], bf[4][2];
#pragma unroll
            for (int mt = 0; mt < 4; mt++) {
                int r = wm + mt * 16 + gid;
                af[mt][0] = As[buf][r][k8 + tig];
                af[mt][1] = As[buf][r + 8][k8 + tig];
                af[mt][2] = As[buf][r][k8 + tig + 4];
                af[mt][3] = As[buf][r + 8][k8 + tig + 4];
            }
#pragma unroll
            for (int nt = 0; nt < 4; nt++) {
                int c = wn + nt * 8 + gid;
                bf[nt][0] = Bs[buf][c][k8 + tig];
                bf[nt][1] = Bs[buf][c][k8 + tig + 4];
            }
#pragma unroll
            for (int mt = 0; mt < 4; mt++)
#pragma unroll
                for (int nt = 0; nt < 4; nt++)
                    mma_tf32(acc[mt][nt], af[mt], bf[nt]);
        }

        if (more) {
            uint4* da = (uint4*)&As[buf ^ 1][lrow][lk];
            uint4* db_ = (uint4*)&Bs[buf ^ 1][lrow][lk];
            da[0] = make_uint4(f2tf32(a0.x), f2tf32(a0.y), f2tf32(a0.z), f2tf32(a0.w));
            da[1] = make_uint4(f2tf32(a1.x), f2tf32(a1.y), f2tf32(a1.z), f2tf32(a1.w));
            db_[0] = make_uint4(f2tf32(b0.x), f2tf32(b0.y), f2tf32(b0.z), f2tf32(b0.w));
            db_[1] = make_uint4(f2tf32(b1.x), f2tf32(b1.y), f2tf32(b1.z), f2tf32(b1.w));
        }
        __syncthreads();
        buf ^= 1;
    }

    // store accumulators
#pragma unroll
    for (int mt = 0; mt < 4; mt++) {
#pragma unroll
        for (int nt = 0; nt < 4; nt++) {
            int m = m0 + wm + mt * 16 + gid;
            int n = n0 + wn + nt * 8 + tig * 2;
            *(float2*)&C[(size_t)m * N + n] = make_float2(acc[mt][nt][0], acc[mt][nt][1]);
            *(float2*)&C[(size_t)(m + 8) * N + n] = make_float2(acc[mt][nt][2], acc[mt][nt][3]);
        }
    }
}

// ---------------- small fp32 GEMM (for Wa/Wb, N=16) -----------------------
#define BM 128
#define BN 128
#define BKK 8
#define TM 8
#define TN 8

__global__ __launch_bounds__(256) void gemm_nt(
    const float* __restrict__ A, const float* __restrict__ B,
    float* __restrict__ C, int M, int N, int K)
{
    __shared__ float As[BKK][BM];
    __shared__ float Bs[BKK][BN];
    int tid = threadIdx.x;
    int tx = tid & 15, ty = tid >> 4;
    int m0 = blockIdx.y * BM, n0 = blockIdx.x * BN;

    int lrow = tid >> 1;
    int lcol = (tid & 1) * 4;
    const float* Ag = A + (size_t)(m0 + lrow) * K + lcol;
    const float* Bg = B + (size_t)(n0 + lrow) * K + lcol;
    bool bvalid = (n0 + lrow) < N;

    float acc[TM][TN];
#pragma unroll
    for (int i = 0; i < TM; i++)
#pragma unroll
        for (int j = 0; j < TN; j++) acc[i][j] = 0.f;

    for (int kb = 0; kb < K; kb += BKK) {
        float4 a4 = *(const float4*)(Ag + kb);
        float4 b4 = make_float4(0.f,0.f,0.f,0.f);
        if (bvalid) b4 = *(const float4*)(Bg + kb);
        As[lcol+0][lrow] = a4.x; As[lcol+1][lrow] = a4.y;
        As[lcol+2][lrow] = a4.z; As[lcol+3][lrow] = a4.w;
        Bs[lcol+0][lrow] = b4.x; Bs[lcol+1][lrow] = b4.y;
        Bs[lcol+2][lrow] = b4.z; Bs[lcol+3][lrow] = b4.w;
        __syncthreads();
#pragma unroll
        for (int kk = 0; kk < BKK; kk++) {
            float ar[TM], br[TN];
            *(float4*)&ar[0] = *(const float4*)&As[kk][ty*TM];
            *(float4*)&ar[4] = *(const float4*)&As[kk][ty*TM+4];
            *(float4*)&br[0] = *(const float4*)&Bs[kk][tx*TN];
            *(float4*)&br[4] = *(const float4*)&Bs[kk][tx*TN+4];
#pragma unroll
            for (int i = 0; i < TM; i++)
#pragma unroll
                for (int j = 0; j < TN; j++)
                    acc[i][j] = fmaf(ar[i], br[j], acc[i][j]);
        }
        __syncthreads();
    }
#pragma unroll
    for (int i = 0; i < TM; i++) {
        int m = m0 + ty*TM + i;
#pragma unroll
        for (int j = 0; j < TN; j += 4) {
            int n = n0 + tx*TN + j;
            if (n + 3 < N) {
                float4 v = make_float4(acc[i][j], acc[i][j+1], acc[i][j+2], acc[i][j+3]);
                *(float4*)&C[(size_t)m * N + n] = v;
            }
        }
    }
}

// ---------------- conv + silu + l2norm for q/k ----------------------------
__global__ __launch_bounds__(128) void convqk_kernel(
    const float* __restrict__ pre, const float* __restrict__ cw,
    float* __restrict__ out, float scale)
{
    int t = blockIdx.x >> 3;
    int h = blockIdx.x & 7;
    int c = threadIdx.x;
    int ch = h * DK + c;
    float y = 0.f;
#pragma unroll
    for (int j = 0; j < CONV; j++) {
        int tt = t - (CONV-1) + j;
        float xv = (tt >= 0) ? pre[(size_t)tt * KEY_DIM + ch] : 0.f;
        y = fmaf(xv, cw[ch*CONV + j], y);
    }
    y = y / (1.f + expf(-y));
    float ss = y * y;
#pragma unroll
    for (int off = 16; off; off >>= 1) ss += __shfl_xor_sync(0xffffffffu, ss, off);
    __shared__ float wss[4];
    if ((threadIdx.x & 31) == 0) wss[threadIdx.x >> 5] = ss;
    __syncthreads();
    float tot = wss[0] + wss[1] + wss[2] + wss[3];
    out[(size_t)t * KEY_DIM + ch] = y * rsqrtf(tot + EPS_) * scale;
}

// ---------------- conv + silu for v ---------------------------------------
__global__ __launch_bounds__(256) void convv_kernel(
    const float* __restrict__ pre, const float* __restrict__ cw,
    float* __restrict__ out)
{
    int idx = blockIdx.x * blockDim.x + threadIdx.x;
    int t = idx >> 11;
    int ch = idx & 2047;
    float y = 0.f;
#pragma unroll
    for (int j = 0; j < CONV; j++) {
        int tt = t - (CONV-1) + j;
        float xv = (tt >= 0) ? pre[(size_t)tt * VAL_DIM + ch] : 0.f;
        y = fmaf(xv, cw[ch*CONV + j], y);
    }
    out[idx] = y / (1.f + expf(-y));
}

// ---------------- decay / beta --------------------------------------------
__global__ __launch_bounds__(256) void db_kernel(
    const float* __restrict__ apre, const float* __restrict__ bpre,
    const float* __restrict__ A_log, const float* __restrict__ dt_bias,
    float2* __restrict__ db)
{
    int idx = blockIdx.x * blockDim.x + threadIdx.x;
    if (idx >= S_LEN * NVH) return;
    int h = idx & (NVH - 1);
    float a = apre[idx] + dt_bias[h];
    float sp = (a > 20.f) ? a : log1pf(expf(a));
    float g = -expf(A_log[h]) * sp;
    float decay = expf(g);
    float beta = 1.f / (1.f + expf(-bpre[idx]));
    db[idx] = make_float2(decay, beta);
}

// ---------------- sequential delta-rule scan ------------------------------
__global__ __launch_bounds__(512) void scan_kernel(
    const float* __restrict__ k, const float* __restrict__ q,
    const float* __restrict__ v, const float2* __restrict__ db,
    float* __restrict__ o)
{
    int h = blockIdx.x >> 1;
    int hk = h >> 1;
    int warp = threadIdx.x >> 5;
    int lane = threadIdx.x & 31;
    int g = lane >> 3;
    int s = lane & 7;
    int col = (blockIdx.x & 1) * 64 + warp * 4 + g;

    const float* kb = k + hk * DK + s * 16;
    const float* qb = q + hk * DK + s * 16;
    const float* vb = v + h * DV + col;
    const float2* dbb = db + h;
    float* ob = o + h * DV + col;

    float S[16];
#pragma unroll
    for (int i = 0; i < 16; i++) S[i] = 0.f;

    float kc[16], qc[16], vc; float2 dc;
#pragma unroll
    for (int i = 0; i < 16; i += 4) {
        *(float4*)&kc[i] = *(const float4*)(kb + i);
        *(float4*)&qc[i] = *(const float4*)(qb + i);
    }
    vc = *vb; dc = *dbb;

#pragma unroll 2
    for (int t = 0; t < S_LEN; t++) {
        int tn = (t + 1 < S_LEN) ? t + 1 : t;
        float kn[16], qn[16], vn; float2 dn;
        const float* kpt = kb + (size_t)tn * KEY_DIM;
        const float* qpt = qb + (size_t)tn * KEY_DIM;
#pragma unroll
        for (int i = 0; i < 16; i += 4) {
            *(float4*)&kn[i] = *(const float4*)(kpt + i);
            *(float4*)&qn[i] = *(const float4*)(qpt + i);
        }
        vn = vb[(size_t)tn * VAL_DIM];
        dn = dbb[(size_t)tn * NVH];

        float a0 = 0.f, a1 = 0.f, a2 = 0.f, a3 = 0.f;
#pragma unroll
        for (int i = 0; i < 16; i += 4) {
            a0 = fmaf(kc[i],   S[i],   a0);
            a1 = fmaf(kc[i+1], S[i+1], a1);
            a2 = fmaf(kc[i+2], S[i+2], a2);
            a3 = fmaf(kc[i+3], S[i+3], a3);
        }
        float p = (a0 + a1) + (a2 + a3);
        p += __shfl_xor_sync(0xffffffffu, p, 1);
        p += __shfl_xor_sync(0xffffffffu, p, 2);
        p += __shfl_xor_sync(0xffffffffu, p, 4);
        float delta = (vc - p * dc.x) * dc.y;

        float b0 = 0.f, b1 = 0.f, b2 = 0.f, b3 = 0.f;
#pragma unroll
        for (int i = 0; i < 16; i += 4) {
            S[i]   = fmaf(S[i],   dc.x, kc[i]   * delta);
            S[i+1] = fmaf(S[i+1], dc.x, kc[i+1] * delta);
            S[i+2] = fmaf(S[i+2], dc.x, kc[i+2] * delta);
            S[i+3] = fmaf(S[i+3], dc.x, kc[i+3] * delta);
            b0 = fmaf(qc[i],   S[i],   b0);
            b1 = fmaf(qc[i+1], S[i+1], b1);
            b2 = fmaf(qc[i+2], S[i+2], b2);
            b3 = fmaf(qc[i+3], S[i+3], b3);
        }
        float ov = (b0 + b1) + (b2 + b3);
        ov += __shfl_xor_sync(0xffffffffu, ov, 1);
        ov += __shfl_xor_sync(0xffffffffu, ov, 2);
        ov += __shfl_xor_sync(0xffffffffu, ov, 4);
        if (s == 0) ob[(size_t)t * VAL_DIM] = ov;

#pragma unroll
        for (int i = 0; i < 16; i++) { kc[i] = kn[i]; qc[i] = qn[i]; }
        vc = vn; dc = dn;
    }
}

// ---------------- gated RMS norm ------------------------------------------
__global__ __launch_bounds__(128) void gnorm_kernel(
    const float* __restrict__ o, const float* __restrict__ gate,
    const float* __restrict__ w_norm, float* __restrict__ og)
{
    int t = blockIdx.x >> 4;
    int h = blockIdx.x & 15;
    int c = threadIdx.x;
    size_t idx = (size_t)t * VAL_DIM + h * DV + c;
    float gt = gate[idx];
    float y = o[idx] * (gt / (1.f + expf(-gt)));
    float ss = y * y;
#pragma unroll
    for (int off = 16; off; off >>= 1) ss += __shfl_xor_sync(0xffffffffu, ss, off);
    __shared__ float wss[4];
    if ((threadIdx.x & 31) == 0) wss[threadIdx.x >> 5] = ss;
    __syncthreads();
    float mean = (wss[0] + wss[1] + wss[2] + wss[3]) * (1.f / DV);
    og[idx] = y * rsqrtf(mean + EPS_) * w_norm[c];
}

// ---------------- launch ---------------------------------------------------
extern "C" void kernel_launch(void* const* d_in, const int* in_sizes, int n_in,
                              void* d_out, int out_size)
{
    const float* x      = (const float*)d_in[0];
    const float* Wq     = (const float*)d_in[1];
    const float* Wk     = (const float*)d_in[2];
    const float* Wv     = (const float*)d_in[3];
    const float* Wa     = (const float*)d_in[4];
    const float* Wb     = (const float*)d_in[5];
    const float* Wg     = (const float*)d_in[6];
    const float* Wo     = (const float*)d_in[7];
    const float* conv_q = (const float*)d_in[8];
    const float* conv_k = (const float*)d_in[9];
    const float* conv_v = (const float*)d_in[10];
    const float* A_log  = (const float*)d_in[11];
    const float* dt_b   = (const float*)d_in[12];
    const float* w_norm = (const float*)d_in[13];

    void* wsp = nullptr;
    cudaGetSymbolAddress(&wsp, g_ws_gdn);
    float* ws = (float*)wsp;
    float* qpre = ws + OF_QPRE;
    float* kpre = ws + OF_KPRE;
    float* vpre = ws + OF_VPRE;
    float* gate = ws + OF_GATE;
    float* apre = ws + OF_APRE;
    float* bpre = ws + OF_BPRE;
    float* qn   = ws + OF_QN;
    float* kn   = ws + OF_KN;
    float* vn   = ws + OF_VN;
    float2* db  = (float2*)(ws + OF_DB);
    float* o    = ws + OF_O;
    float* og   = ws + OF_OG;
    float* out  = (float*)d_out;

    dim3 blk(256);
    dim3 g_qk(KEY_DIM / GBN, S_LEN / GBM);   // (8,32)
    dim3 g_v (VAL_DIM / GBN, S_LEN / GBM);   // (16,32)
    dim3 g_ab(1, S_LEN / BM);                // small gemm

    gemm_tf32<<<g_qk, blk>>>(x, Wq, qpre, S_LEN, KEY_DIM, HID);
    gemm_tf32<<<g_qk, blk>>>(x, Wk, kpre, S_LEN, KEY_DIM, HID);
    gemm_tf32<<<g_v,  blk>>>(x, Wv, vpre, S_LEN, VAL_DIM, HID);
    gemm_tf32<<<g_v,  blk>>>(x, Wg, gate, S_LEN, VAL_DIM, HID);
    gemm_nt<<<g_ab, blk>>>(x, Wa, apre, S_LEN, NVH, HID);
    gemm_nt<<<g_ab, blk>>>(x, Wb, bpre, S_LEN, NVH, HID);

    convqk_kernel<<<S_LEN * NH, 128>>>(qpre, conv_q, qn, SCALE_);
    convqk_kernel<<<S_LEN * NH, 128>>>(kpre, conv_k, kn, 1.f);
    convv_kernel<<<(S_LEN * VAL_DIM) / 256, 256>>>(vpre, conv_v, vn);
    db_kernel<<<(S_LEN * NVH + 255) / 256, 256>>>(apre, bpre, A_log, dt_b, db);

    scan_kernel<<<32, 512>>>(kn, qn, vn, db, o);

    gnorm_kernel<<<S_LEN * NVH, 128>>>(o, gate, w_norm, og);

    gemm_tf32<<<g_v, blk>>>(og, Wo, out, S_LEN, HID, VAL_DIM);
}

// round 5
// speedup vs baseline: 3.1227x; 2.2808x over previous
#include <cuda_runtime.h>
#include <math.h>
#include <stdint.h>

// ---------------- problem constants ----------------
#define S_LEN 4096
#define HID   2048
#define NH    8
#define NVH   16
#define DK    128
#define DV    128
#define KEY_DIM  (NH*DK)    // 1024
#define VAL_DIM  (NVH*DV)   // 2048
#define CONV  4
#define EPS_  1e-6f
#define SCALE_ 0.08838834764831845f   // 128^-0.5

// ---------------- workspace -------------------------------------------------
static constexpr size_t SZ_QPRE = (size_t)S_LEN * KEY_DIM;
static constexpr size_t SZ_VPRE = (size_t)S_LEN * VAL_DIM;
static constexpr size_t SZ_AB   = (size_t)S_LEN * NVH;

static constexpr size_t OF_QPRE = 0;
static constexpr size_t OF_KPRE = OF_QPRE + SZ_QPRE;
static constexpr size_t OF_VPRE = OF_KPRE + SZ_QPRE;
static constexpr size_t OF_GATE = OF_VPRE + SZ_VPRE;
static constexpr size_t OF_QN   = OF_GATE + SZ_VPRE;
static constexpr size_t OF_KN   = OF_QN + SZ_QPRE;
static constexpr size_t OF_VN   = OF_KN + SZ_QPRE;
static constexpr size_t OF_DB   = OF_VN + SZ_VPRE;           // float2 per (t,h)
static constexpr size_t OF_O    = OF_DB + 2*SZ_AB;
static constexpr size_t OF_OG   = OF_O + SZ_VPRE;
static constexpr size_t WS_TOTAL = OF_OG + SZ_VPRE;

__device__ float g_ws_gdn[WS_TOTAL];

// ---------------- cp.async helpers -----------------------------------------
__device__ __forceinline__ void cp16(void* s, const void* g) {
    asm volatile("cp.async.ca.shared.global [%0], [%1], 16;"
                 :: "r"((uint32_t)__cvta_generic_to_shared(s)), "l"(g));
}
__device__ __forceinline__ void cp8(void* s, const void* g) {
    asm volatile("cp.async.ca.shared.global [%0], [%1], 8;"
                 :: "r"((uint32_t)__cvta_generic_to_shared(s)), "l"(g));
}
__device__ __forceinline__ void cp_commit() {
    asm volatile("cp.async.commit_group;");
}

// ================= tf32 tensor-core GEMM ==================================
#define GBM 128
#define GBN 128
#define GBK 16

__device__ __forceinline__ uint32_t f2tf32(float x) {
    uint32_t r;
    asm("cvt.rna.tf32.f32 %0, %1;" : "=r"(r) : "f"(x));
    return r;
}

__device__ __forceinline__ void mma_tf32(float* c, const uint32_t* a, const uint32_t* b) {
    asm volatile(
        "mma.sync.aligned.m16n8k8.row.col.f32.tf32.tf32.f32 "
        "{%0,%1,%2,%3}, {%4,%5,%6,%7}, {%8,%9}, {%0,%1,%2,%3};"
        : "+f"(c[0]), "+f"(c[1]), "+f"(c[2]), "+f"(c[3])
        : "r"(a[0]), "r"(a[1]), "r"(a[2]), "r"(a[3]), "r"(b[0]), "r"(b[1]));
}

__global__ __launch_bounds__(256) void gemm_tf32(
    const float* __restrict__ A, const float* __restrict__ B,
    float* __restrict__ C, int M, int N, int K)
{
    __shared__ uint32_t As[2][GBM][GBK + 4];
    __shared__ uint32_t Bs[2][GBN][GBK + 4];

    int tid = threadIdx.x;
    int warp = tid >> 5;
    int lane = tid & 31;
    int gid = lane >> 2;
    int tig = lane & 3;

    int m0 = blockIdx.y * GBM;
    int n0 = blockIdx.x * GBN;
    int wm = (warp >> 2) * 64;
    int wn = (warp & 3) * 32;

    int lrow = tid >> 1;
    int lk   = (tid & 1) * 8;
    const float* Ag = A + (size_t)(m0 + lrow) * K + lk;
    const float* Bg = B + (size_t)(n0 + lrow) * K + lk;

    float acc[4][4][4];
#pragma unroll
    for (int i = 0; i < 4; i++)
#pragma unroll
        for (int j = 0; j < 4; j++)
#pragma unroll
            for (int r = 0; r < 4; r++) acc[i][j][r] = 0.f;

    int kIters = K / GBK;

    float4 a0 = *(const float4*)(Ag);
    float4 a1 = *(const float4*)(Ag + 4);
    float4 b0 = *(const float4*)(Bg);
    float4 b1 = *(const float4*)(Bg + 4);
    {
        uint4* da = (uint4*)&As[0][lrow][lk];
        uint4* db_ = (uint4*)&Bs[0][lrow][lk];
        da[0] = make_uint4(f2tf32(a0.x), f2tf32(a0.y), f2tf32(a0.z), f2tf32(a0.w));
        da[1] = make_uint4(f2tf32(a1.x), f2tf32(a1.y), f2tf32(a1.z), f2tf32(a1.w));
        db_[0] = make_uint4(f2tf32(b0.x), f2tf32(b0.y), f2tf32(b0.z), f2tf32(b0.w));
        db_[1] = make_uint4(f2tf32(b1.x), f2tf32(b1.y), f2tf32(b1.z), f2tf32(b1.w));
    }
    __syncthreads();

    int buf = 0;
    for (int it = 0; it < kIters; it++) {
        bool more = (it + 1) < kIters;
        if (more) {
            const float* Agn = Ag + (size_t)(it + 1) * GBK;
            const float* Bgn = Bg + (size_t)(it + 1) * GBK;
            a0 = *(const float4*)(Agn);
            a1 = *(const float4*)(Agn + 4);
            b0 = *(const float4*)(Bgn);
            b1 = *(const float4*)(Bgn + 4);
        }

#pragma unroll
        for (int s = 0; s < 2; s++) {
            int k8 = s * 8;
            uint32_t af[4][4], bf[4][2];
#pragma unroll
            for (int mt = 0; mt < 4; mt++) {
                int r = wm + mt * 16 + gid;
                af[mt][0] = As[buf][r][k8 + tig];
                af[mt][1] = As[buf][r + 8][k8 + tig];
                af[mt][2] = As[buf][r][k8 + tig + 4];
                af[mt][3] = As[buf][r + 8][k8 + tig + 4];
            }
#pragma unroll
            for (int nt = 0; nt < 4; nt++) {
                int c = wn + nt * 8 + gid;
                bf[nt][0] = Bs[buf][c][k8 + tig];
                bf[nt][1] = Bs[buf][c][k8 + tig + 4];
            }
#pragma unroll
            for (int mt = 0; mt < 4; mt++)
#pragma unroll
                for (int nt = 0; nt < 4; nt++)
                    mma_tf32(acc[mt][nt], af[mt], bf[nt]);
        }

        if (more) {
            uint4* da = (uint4*)&As[buf ^ 1][lrow][lk];
            uint4* db_ = (uint4*)&Bs[buf ^ 1][lrow][lk];
            da[0] = make_uint4(f2tf32(a0.x), f2tf32(a0.y), f2tf32(a0.z), f2tf32(a0.w));
            da[1] = make_uint4(f2tf32(a1.x), f2tf32(a1.y), f2tf32(a1.z), f2tf32(a1.w));
            db_[0] = make_uint4(f2tf32(b0.x), f2tf32(b0.y), f2tf32(b0.z), f2tf32(b0.w));
            db_[1] = make_uint4(f2tf32(b1.x), f2tf32(b1.y), f2tf32(b1.z), f2tf32(b1.w));
        }
        __syncthreads();
        buf ^= 1;
    }

#pragma unroll
    for (int mt = 0; mt < 4; mt++) {
#pragma unroll
        for (int nt = 0; nt < 4; nt++) {
            int m = m0 + wm + mt * 16 + gid;
            int n = n0 + wn + nt * 8 + tig * 2;
            *(float2*)&C[(size_t)m * N + n] = make_float2(acc[mt][nt][0], acc[mt][nt][1]);
            *(float2*)&C[(size_t)(m + 8) * N + n] = make_float2(acc[mt][nt][2], acc[mt][nt][3]);
        }
    }
}

// ---------------- fused a/b projection + decay/beta (N=16 each) -----------
// db[t][h] = (decay, beta). Block: 8 rows, thread (row, n).
__global__ __launch_bounds__(128) void gemv_ab(
    const float* __restrict__ x, const float* __restrict__ Wa,
    const float* __restrict__ Wb, const float* __restrict__ A_log,
    const float* __restrict__ dt_bias, float2* __restrict__ db)
{
    __shared__ float xs[8][260];
    __shared__ float was[16][260];
    __shared__ float wbs[16][260];

    int tid = threadIdx.x;
    int row = tid >> 4, n = tid & 15;
    int r0 = blockIdx.x * 8;

    float acc_a = 0.f, acc_b = 0.f;
    for (int kc = 0; kc < HID; kc += 256) {
        __syncthreads();
        int lr = tid >> 4, lo = (tid & 15) * 16;
#pragma unroll
        for (int j = 0; j < 16; j += 4)
            *(float4*)&xs[lr][lo + j] = *(const float4*)&x[(size_t)(r0 + lr) * HID + kc + lo + j];
        int wr = tid >> 3, wo = (tid & 7) * 32;
#pragma unroll
        for (int j = 0; j < 32; j += 4) {
            *(float4*)&was[wr][wo + j] = *(const float4*)&Wa[(size_t)wr * HID + kc + wo + j];
            *(float4*)&wbs[wr][wo + j] = *(const float4*)&Wb[(size_t)wr * HID + kc + wo + j];
        }
        __syncthreads();
#pragma unroll 8
        for (int j = 0; j < 256; j += 4) {
            float4 xv = *(float4*)&xs[row][j];
            float4 wa = *(float4*)&was[n][j];
            float4 wb = *(float4*)&wbs[n][j];
            acc_a += xv.x*wa.x + xv.y*wa.y + xv.z*wa.z + xv.w*wa.w;
            acc_b += xv.x*wb.x + xv.y*wb.y + xv.z*wb.z + xv.w*wb.w;
        }
    }
    float a = acc_a + dt_bias[n];
    float sp = (a > 20.f) ? a : log1pf(expf(a));
    float decay = expf(-expf(A_log[n]) * sp);
    float beta = 1.f / (1.f + expf(-acc_b));
    db[(size_t)(r0 + row) * NVH + n] = make_float2(decay, beta);
}

// ---------------- conv + silu + l2norm for q/k ----------------------------
__global__ __launch_bounds__(128) void convqk_kernel(
    const float* __restrict__ pre, const float* __restrict__ cw,
    float* __restrict__ out, float scale)
{
    int t = blockIdx.x >> 3;
    int h = blockIdx.x & 7;
    int c = threadIdx.x;
    int ch = h * DK + c;
    float y = 0.f;
#pragma unroll
    for (int j = 0; j < CONV; j++) {
        int tt = t - (CONV-1) + j;
        float xv = (tt >= 0) ? pre[(size_t)tt * KEY_DIM + ch] : 0.f;
        y = fmaf(xv, cw[ch*CONV + j], y);
    }
    y = y / (1.f + expf(-y));
    float ss = y * y;
#pragma unroll
    for (int off = 16; off; off >>= 1) ss += __shfl_xor_sync(0xffffffffu, ss, off);
    __shared__ float wss[4];
    if ((threadIdx.x & 31) == 0) wss[threadIdx.x >> 5] = ss;
    __syncthreads();
    float tot = wss[0] + wss[1] + wss[2] + wss[3];
    out[(size_t)t * KEY_DIM + ch] = y * rsqrtf(tot + EPS_) * scale;
}

// ---------------- conv + silu for v ---------------------------------------
__global__ __launch_bounds__(256) void convv_kernel(
    const float* __restrict__ pre, const float* __restrict__ cw,
    float* __restrict__ out)
{
    int idx = blockIdx.x * blockDim.x + threadIdx.x;
    int t = idx >> 11;
    int ch = idx & 2047;
    float y = 0.f;
#pragma unroll
    for (int j = 0; j < CONV; j++) {
        int tt = t - (CONV-1) + j;
        float xv = (tt >= 0) ? pre[(size_t)tt * VAL_DIM + ch] : 0.f;
        y = fmaf(xv, cw[ch*CONV + j], y);
    }
    out[idx] = y / (1.f + expf(-y));
}

// ---------------- sequential delta-rule scan v2 ---------------------------
// 128 blocks x 128 threads. Block: head h = blk>>3, cols (blk&7)*16 .. +16.
// Warp w handles 4 columns; 8 lanes per column, 16 state elems per lane.
// k/q/v/db staged in double-buffered smem via cp.async, CH steps per chunk.
#define CH 16

__global__ __launch_bounds__(128) void scan_kernel(
    const float* __restrict__ k, const float* __restrict__ q,
    const float* __restrict__ v, const float2* __restrict__ db,
    float* __restrict__ o)
{
    __shared__ float ks[2][CH][DK];
    __shared__ float qs[2][CH][DK];
    __shared__ float vs[2][CH][16];
    __shared__ float2 dbs[2][CH];

    int h = blockIdx.x >> 3;
    int hk = h >> 1;
    int colbase = (blockIdx.x & 7) * 16;
    int tid = threadIdx.x;
    int w = tid >> 5, lane = tid & 31;
    int g = lane >> 3, s = lane & 7;
    int col = colbase + w * 4 + g;

    // chunk-load duty mapping
    int lr = tid >> 3;            // 0..15 row within chunk (k/q)
    int lo = (tid & 7) * 16;      // 16 floats per thread
    int vr = tid >> 2;            // 0..31 (only tid<64 used)
    int vo = (tid & 3) * 4;

    const float* kbase = k + hk * DK + lo;
    const float* qbase = q + hk * DK + lo;
    const float* vbase = v + h * DV + colbase + vo;
    const float2* dbase = db + h;

    // issue chunk 0
    {
        int t0 = 0;
#pragma unroll
        for (int j = 0; j < 4; j++) {
            cp16(&ks[0][lr][lo + j*4], kbase + (size_t)(t0 + lr) * KEY_DIM + j*4);
            cp16(&qs[0][lr][lo + j*4], qbase + (size_t)(t0 + lr) * KEY_DIM + j*4);
        }
        if (tid < 64) cp16(&vs[0][vr][(tid & 3) * 4], vbase + (size_t)(t0 + vr) * VAL_DIM);
        if (tid < CH) cp8(&dbs[0][tid], dbase + (size_t)(t0 + tid) * NVH);
        cp_commit();
    }

    float S[16];
#pragma unroll
    for (int i = 0; i < 16; i++) S[i] = 0.f;

    int buf = 0;
    const int NCH = S_LEN / CH;
    for (int c = 0; c < NCH; c++) {
        if (c + 1 < NCH) {
            int t0 = (c + 1) * CH;
            int p = buf ^ 1;
#pragma unroll
            for (int j = 0; j < 4; j++) {
                cp16(&ks[p][lr][lo + j*4], kbase + (size_t)(t0 + lr) * KEY_DIM + j*4);
                cp16(&qs[p][lr][lo + j*4], qbase + (size_t)(t0 + lr) * KEY_DIM + j*4);
            }
            if (tid < 64) cp16(&vs[p][vr][(tid & 3) * 4], vbase + (size_t)(t0 + vr) * VAL_DIM);
            if (tid < CH) cp8(&dbs[p][tid], dbase + (size_t)(t0 + tid) * NVH);
            cp_commit();
            asm volatile("cp.async.wait_group 1;");
        } else {
            asm volatile("cp.async.wait_group 0;");
        }
        __syncthreads();

        int t0 = c * CH;
        float* ob = o + (size_t)t0 * VAL_DIM + h * DV + col;
#pragma unroll
        for (int tt = 0; tt < CH; tt++) {
            float kc[16], qc[16];
#pragma unroll
            for (int i = 0; i < 16; i += 4) {
                *(float4*)&kc[i] = *(const float4*)&ks[buf][tt][s * 16 + i];
                *(float4*)&qc[i] = *(const float4*)&qs[buf][tt][s * 16 + i];
            }
            float vc = vs[buf][tt][w * 4 + g];
            float2 dc = dbs[buf][tt];

            // pred = decay * (k . S_old)
            float a0 = 0.f, a1 = 0.f, a2 = 0.f, a3 = 0.f;
#pragma unroll
            for (int i = 0; i < 16; i += 4) {
                a0 = fmaf(kc[i],   S[i],   a0);
                a1 = fmaf(kc[i+1], S[i+1], a1);
                a2 = fmaf(kc[i+2], S[i+2], a2);
                a3 = fmaf(kc[i+3], S[i+3], a3);
            }
            float p = (a0 + a1) + (a2 + a3);
            p += __shfl_xor_sync(0xffffffffu, p, 1);
            p += __shfl_xor_sync(0xffffffffu, p, 2);
            p += __shfl_xor_sync(0xffffffffu, p, 4);
            float delta = (vc - p * dc.x) * dc.y;

            // S = decay*S + k*delta ; o = q . S_new
            float b0 = 0.f, b1 = 0.f, b2 = 0.f, b3 = 0.f;
#pragma unroll
            for (int i = 0; i < 16; i += 4) {
                S[i]   = fmaf(S[i],   dc.x, kc[i]   * delta);
                S[i+1] = fmaf(S[i+1], dc.x, kc[i+1] * delta);
                S[i+2] = fmaf(S[i+2], dc.x, kc[i+2] * delta);
                S[i+3] = fmaf(S[i+3], dc.x, kc[i+3] * delta);
                b0 = fmaf(qc[i],   S[i],   b0);
                b1 = fmaf(qc[i+1], S[i+1], b1);
                b2 = fmaf(qc[i+2], S[i+2], b2);
                b3 = fmaf(qc[i+3], S[i+3], b3);
            }
            float ov = (b0 + b1) + (b2 + b3);
            ov += __shfl_xor_sync(0xffffffffu, ov, 1);
            ov += __shfl_xor_sync(0xffffffffu, ov, 2);
            ov += __shfl_xor_sync(0xffffffffu, ov, 4);
            if (s == 0) ob[(size_t)tt * VAL_DIM] = ov;
        }
        __syncthreads();
        buf ^= 1;
    }
}

// ---------------- gated RMS norm ------------------------------------------
__global__ __launch_bounds__(128) void gnorm_kernel(
    const float* __restrict__ o, const float* __restrict__ gate,
    const float* __restrict__ w_norm, float* __restrict__ og)
{
    int t = blockIdx.x >> 4;
    int h = blockIdx.x & 15;
    int c = threadIdx.x;
    size_t idx = (size_t)t * VAL_DIM + h * DV + c;
    float gt = gate[idx];
    float y = o[idx] * (gt / (1.f + expf(-gt)));
    float ss = y * y;
#pragma unroll
    for (int off = 16; off; off >>= 1) ss += __shfl_xor_sync(0xffffffffu, ss, off);
    __shared__ float wss[4];
    if ((threadIdx.x & 31) == 0) wss[threadIdx.x >> 5] = ss;
    __syncthreads();
    float mean = (wss[0] + wss[1] + wss[2] + wss[3]) * (1.f / DV);
    og[idx] = y * rsqrtf(mean + EPS_) * w_norm[c];
}

// ---------------- launch ---------------------------------------------------
extern "C" void kernel_launch(void* const* d_in, const int* in_sizes, int n_in,
                              void* d_out, int out_size)
{
    const float* x      = (const float*)d_in[0];
    const float* Wq     = (const float*)d_in[1];
    const float* Wk     = (const float*)d_in[2];
    const float* Wv     = (const float*)d_in[3];
    const float* Wa     = (const float*)d_in[4];
    const float* Wb     = (const float*)d_in[5];
    const float* Wg     = (const float*)d_in[6];
    const float* Wo     = (const float*)d_in[7];
    const float* conv_q = (const float*)d_in[8];
    const float* conv_k = (const float*)d_in[9];
    const float* conv_v = (const float*)d_in[10];
    const float* A_log  = (const float*)d_in[11];
    const float* dt_b   = (const float*)d_in[12];
    const float* w_norm = (const float*)d_in[13];

    void* wsp = nullptr;
    cudaGetSymbolAddress(&wsp, g_ws_gdn);
    float* ws = (float*)wsp;
    float* qpre = ws + OF_QPRE;
    float* kpre = ws + OF_KPRE;
    float* vpre = ws + OF_VPRE;
    float* gate = ws + OF_GATE;
    float* qn   = ws + OF_QN;
    float* kn   = ws + OF_KN;
    float* vn   = ws + OF_VN;
    float2* db  = (float2*)(ws + OF_DB);
    float* o    = ws + OF_O;
    float* og   = ws + OF_OG;
    float* out  = (float*)d_out;

    dim3 blk(256);
    dim3 g_qk(KEY_DIM / GBN, S_LEN / GBM);   // (8,32)
    dim3 g_v (VAL_DIM / GBN, S_LEN / GBM);   // (16,32)

    gemm_tf32<<<g_qk, blk>>>(x, Wq, qpre, S_LEN, KEY_DIM, HID);
    gemm_tf32<<<g_qk, blk>>>(x, Wk, kpre, S_LEN, KEY_DIM, HID);
    gemm_tf32<<<g_v,  blk>>>(x, Wv, vpre, S_LEN, VAL_DIM, HID);
    gemm_tf32<<<g_v,  blk>>>(x, Wg, gate, S_LEN, VAL_DIM, HID);
    gemv_ab<<<S_LEN / 8, 128>>>(x, Wa, Wb, A_log, dt_b, db);

    convqk_kernel<<<S_LEN * NH, 128>>>(qpre, conv_q, qn, SCALE_);
    convqk_kernel<<<S_LEN * NH, 128>>>(kpre, conv_k, kn, 1.f);
    convv_kernel<<<(S_LEN * VAL_DIM) / 256, 256>>>(vpre, conv_v, vn);

    scan_kernel<<<128, 128>>>(kn, qn, vn, db, o);

    gnorm_kernel<<<S_LEN * NVH, 128>>>(o, gate, w_norm, og);

    gemm_tf32<<<g_v, blk>>>(og, Wo, out, S_LEN, HID, VAL_DIM);
}

// round 7
// speedup vs baseline: 3.3191x; 1.0629x over previous
#include <cuda_runtime.h>
#include <math.h>
#include <stdint.h>

// ---------------- problem constants ----------------
#define S_LEN 4096
#define HID   2048
#define NH    8
#define NVH   16
#define DK    128
#define DV    128
#define KEY_DIM  (NH*DK)    // 1024
#define VAL_DIM  (NVH*DV)   // 2048
#define CONV  4
#define EPS_  1e-6f
#define SCALE_ 0.08838834764831845f   // 128^-0.5

// ---------------- workspace -------------------------------------------------
static constexpr size_t SZ_QPRE = (size_t)S_LEN * KEY_DIM;
static constexpr size_t SZ_VPRE = (size_t)S_LEN * VAL_DIM;
static constexpr size_t SZ_AB   = (size_t)S_LEN * NVH;
static constexpr size_t SZ_C    = (size_t)S_LEN * NH;

static constexpr size_t OF_QPRE = 0;
static constexpr size_t OF_KPRE = OF_QPRE + SZ_QPRE;
static constexpr size_t OF_VPRE = OF_KPRE + SZ_QPRE;
static constexpr size_t OF_GATE = OF_VPRE + SZ_VPRE;
static constexpr size_t OF_QN   = OF_GATE + SZ_VPRE;
static constexpr size_t OF_KN   = OF_QN + SZ_QPRE;
static constexpr size_t OF_VN   = OF_KN + SZ_QPRE;
static constexpr size_t OF_DB   = OF_VN + SZ_VPRE;   // float2 per (t,h)
static constexpr size_t OF_CQ   = OF_DB + 2*SZ_AB;   // C[t][hk]
static constexpr size_t OF_O    = OF_CQ + SZ_C;
static constexpr size_t OF_OG   = OF_O + SZ_VPRE;
static constexpr size_t WS_TOTAL = OF_OG + SZ_VPRE;

__device__ float g_ws_gdn[WS_TOTAL];

// ---------------- cp.async helpers -----------------------------------------
__device__ __forceinline__ void cp16(void* s, const void* g) {
    asm volatile("cp.async.ca.shared.global [%0], [%1], 16;"
                 :: "r"((uint32_t)__cvta_generic_to_shared(s)), "l"(g));
}
__device__ __forceinline__ void cp8(void* s, const void* g) {
    asm volatile("cp.async.ca.shared.global [%0], [%1], 8;"
                 :: "r"((uint32_t)__cvta_generic_to_shared(s)), "l"(g));
}
__device__ __forceinline__ void cp4(void* s, const void* g) {
    asm volatile("cp.async.ca.shared.global [%0], [%1], 4;"
                 :: "r"((uint32_t)__cvta_generic_to_shared(s)), "l"(g));
}
__device__ __forceinline__ void cp_commit() {
    asm volatile("cp.async.commit_group;");
}

// ================= tf32 tensor-core GEMM core =============================
#define GBM 128
#define GBN 128
#define GBK 16

__device__ __forceinline__ uint32_t f2tf32(float x) {
    uint32_t r;
    asm("cvt.rna.tf32.f32 %0, %1;" : "=r"(r) : "f"(x));
    return r;
}

__device__ __forceinline__ void mma_tf32(float* c, const uint32_t* a, const uint32_t* b) {
    asm volatile(
        "mma.sync.aligned.m16n8k8.row.col.f32.tf32.tf32.f32 "
        "{%0,%1,%2,%3}, {%4,%5,%6,%7}, {%8,%9}, {%0,%1,%2,%3};"
        : "+f"(c[0]), "+f"(c[1]), "+f"(c[2]), "+f"(c[3])
        : "r"(a[0]), "r"(a[1]), "r"(a[2]), "r"(a[3]), "r"(b[0]), "r"(b[1]));
}

// C[m0.., n0..] = A[M,K] * B[n0..,K]^T ; C row stride ldc. K multiple of 16.
__device__ __forceinline__ void gemm_core(
    const float* __restrict__ A, const float* __restrict__ B,
    float* __restrict__ C, int n0, int ldc, int K)
{
    __shared__ uint32_t As[2][GBM][GBK + 4];
    __shared__ uint32_t Bs[2][GBN][GBK + 4];

    int tid = threadIdx.x;
    int warp = tid >> 5;
    int lane = tid & 31;
    int gid = lane >> 2;
    int tig = lane & 3;

    int m0 = blockIdx.y * GBM;
    int wm = (warp >> 2) * 64;
    int wn = (warp & 3) * 32;

    int lrow = tid >> 1;
    int lk   = (tid & 1) * 8;
    const float* Ag = A + (size_t)(m0 + lrow) * K + lk;
    const float* Bg = B + (size_t)(n0 + lrow) * K + lk;

    float acc[4][4][4];
#pragma unroll
    for (int i = 0; i < 4; i++)
#pragma unroll
        for (int j = 0; j < 4; j++)
#pragma unroll
            for (int r = 0; r < 4; r++) acc[i][j][r] = 0.f;

    int kIters = K / GBK;

    float4 a0 = *(const float4*)(Ag);
    float4 a1 = *(const float4*)(Ag + 4);
    float4 b0 = *(const float4*)(Bg);
    float4 b1 = *(const float4*)(Bg + 4);
    {
        uint4* da = (uint4*)&As[0][lrow][lk];
        uint4* db_ = (uint4*)&Bs[0][lrow][lk];
        da[0] = make_uint4(f2tf32(a0.x), f2tf32(a0.y), f2tf32(a0.z), f2tf32(a0.w));
        da[1] = make_uint4(f2tf32(a1.x), f2tf32(a1.y), f2tf32(a1.z), f2tf32(a1.w));
        db_[0] = make_uint4(f2tf32(b0.x), f2tf32(b0.y), f2tf32(b0.z), f2tf32(b0.w));
        db_[1] = make_uint4(f2tf32(b1.x), f2tf32(b1.y), f2tf32(b1.z), f2tf32(b1.w));
    }
    __syncthreads();

    int buf = 0;
    for (int it = 0; it < kIters; it++) {
        bool more = (it + 1) < kIters;
        if (more) {
            const float* Agn = Ag + (size_t)(it + 1) * GBK;
            const float* Bgn = Bg + (size_t)(it + 1) * GBK;
            a0 = *(const float4*)(Agn);
            a1 = *(const float4*)(Agn + 4);
            b0 = *(const float4*)(Bgn);
            b1 = *(const float4*)(Bgn + 4);
        }

#pragma unroll
        for (int s = 0; s < 2; s++) {
            int k8 = s * 8;
            uint32_t af[4][4], bf[4][2];
#pragma unroll
            for (int mt = 0; mt < 4; mt++) {
                int r = wm + mt * 16 + gid;
                af[mt][0] = As[buf][r][k8 + tig];
                af[mt][1] = As[buf][r + 8][k8 + tig];
                af[mt][2] = As[buf][r][k8 + tig + 4];
                af[mt][3] = As[buf][r + 8][k8 + tig + 4];
            }
#pragma unroll
            for (int nt = 0; nt < 4; nt++) {
                int c = wn + nt * 8 + gid;
                bf[nt][0] = Bs[buf][c][k8 + tig];
                bf[nt][1] = Bs[buf][c][k8 + tig + 4];
            }
#pragma unroll
            for (int mt = 0; mt < 4; mt++)
#pragma unroll
                for (int nt = 0; nt < 4; nt++)
                    mma_tf32(acc[mt][nt], af[mt], bf[nt]);
        }

        if (more) {
            uint4* da = (uint4*)&As[buf ^ 1][lrow][lk];
            uint4* db_ = (uint4*)&Bs[buf ^ 1][lrow][lk];
            da[0] = make_uint4(f2tf32(a0.x), f2tf32(a0.y), f2tf32(a0.z), f2tf32(a0.w));
            da[1] = make_uint4(f2tf32(a1.x), f2tf32(a1.y), f2tf32(a1.z), f2tf32(a1.w));
            db_[0] = make_uint4(f2tf32(b0.x), f2tf32(b0.y), f2tf32(b0.z), f2tf32(b0.w));
            db_[1] = make_uint4(f2tf32(b1.x), f2tf32(b1.y), f2tf32(b1.z), f2tf32(b1.w));
        }
        __syncthreads();
        buf ^= 1;
    }

#pragma unroll
    for (int mt = 0; mt < 4; mt++) {
#pragma unroll
        for (int nt = 0; nt < 4; nt++) {
            int m = m0 + wm + mt * 16 + gid;
            int n = n0 + wn + nt * 8 + tig * 2;
            *(float2*)&C[(size_t)m * ldc + n] = make_float2(acc[mt][nt][0], acc[mt][nt][1]);
            *(float2*)&C[(size_t)(m + 8) * ldc + n] = make_float2(acc[mt][nt][2], acc[mt][nt][3]);
        }
    }
}

// merged x-projection: blockIdx.x 0..7 Wq, 8..15 Wk, 16..31 Wv, 32..47 Wg
__global__ __launch_bounds__(256) void gemm_x4(
    const float* __restrict__ x,
    const float* __restrict__ Wq, const float* __restrict__ Wk,
    const float* __restrict__ Wv, const float* __restrict__ Wg,
    float* __restrict__ qpre, float* __restrict__ kpre,
    float* __restrict__ vpre, float* __restrict__ gate)
{
    int bx = blockIdx.x;
    const float* B; float* C; int n0; int ldc;
    if (bx < 8)       { B = Wq; C = qpre; n0 = bx * 128;        ldc = KEY_DIM; }
    else if (bx < 16) { B = Wk; C = kpre; n0 = (bx - 8) * 128;  ldc = KEY_DIM; }
    else if (bx < 32) { B = Wv; C = vpre; n0 = (bx - 16) * 128; ldc = VAL_DIM; }
    else              { B = Wg; C = gate; n0 = (bx - 32) * 128; ldc = VAL_DIM; }
    gemm_core(x, B, C, n0, ldc, HID);
}

__global__ __launch_bounds__(256) void gemm_tf32(
    const float* __restrict__ A, const float* __restrict__ B,
    float* __restrict__ C, int N, int K)
{
    gemm_core(A, B, C, blockIdx.x * GBN, N, K);
}

// ---------------- fused a/b projection + decay/beta -----------------------
__global__ __launch_bounds__(128) void gemv_ab(
    const float* __restrict__ x, const float* __restrict__ Wa,
    const float* __restrict__ Wb, const float* __restrict__ A_log,
    const float* __restrict__ dt_bias, float2* __restrict__ db)
{
    __shared__ float xs[8][260];
    __shared__ float was[16][260];
    __shared__ float wbs[16][260];

    int tid = threadIdx.x;
    int row = tid >> 4, n = tid & 15;
    int r0 = blockIdx.x * 8;

    float acc_a = 0.f, acc_b = 0.f;
    for (int kc = 0; kc < HID; kc += 256) {
        __syncthreads();
        int lr = tid >> 4, lo = (tid & 15) * 16;
#pragma unroll
        for (int j = 0; j < 16; j += 4)
            *(float4*)&xs[lr][lo + j] = *(const float4*)&x[(size_t)(r0 + lr) * HID + kc + lo + j];
        int wr = tid >> 3, wo = (tid & 7) * 32;
#pragma unroll
        for (int j = 0; j < 32; j += 4) {
            *(float4*)&was[wr][wo + j] = *(const float4*)&Wa[(size_t)wr * HID + kc + wo + j];
            *(float4*)&wbs[wr][wo + j] = *(const float4*)&Wb[(size_t)wr * HID + kc + wo + j];
        }
        __syncthreads();
#pragma unroll 8
        for (int j = 0; j < 256; j += 4) {
            float4 xv = *(float4*)&xs[row][j];
            float4 wa = *(float4*)&was[n][j];
            float4 wb = *(float4*)&wbs[n][j];
            acc_a += xv.x*wa.x + xv.y*wa.y + xv.z*wa.z + xv.w*wa.w;
            acc_b += xv.x*wb.x + xv.y*wb.y + xv.z*wb.z + xv.w*wb.w;
        }
    }
    float a = acc_a + dt_bias[n];
    float sp = (a > 20.f) ? a : log1pf(expf(a));
    float decay = expf(-expf(A_log[n]) * sp);
    float beta = 1.f / (1.f + expf(-acc_b));
    db[(size_t)(r0 + row) * NVH + n] = make_float2(decay, beta);
}

// ---------------- conv + silu + l2norm for q/k ----------------------------
__global__ __launch_bounds__(128) void convqk_kernel(
    const float* __restrict__ pre, const float* __restrict__ cw,
    float* __restrict__ out, float scale)
{
    int t = blockIdx.x >> 3;
    int h = blockIdx.x & 7;
    int c = threadIdx.x;
    int ch = h * DK + c;
    float y = 0.f;
#pragma unroll
    for (int j = 0; j < CONV; j++) {
        int tt = t - (CONV-1) + j;
        float xv = (tt >= 0) ? pre[(size_t)tt * KEY_DIM + ch] : 0.f;
        y = fmaf(xv, cw[ch*CONV + j], y);
    }
    y = y / (1.f + expf(-y));
    float ss = y * y;
#pragma unroll
    for (int off = 16; off; off >>= 1) ss += __shfl_xor_sync(0xffffffffu, ss, off);
    __shared__ float wss[4];
    if ((threadIdx.x & 31) == 0) wss[threadIdx.x >> 5] = ss;
    __syncthreads();
    float tot = wss[0] + wss[1] + wss[2] + wss[3];
    out[(size_t)t * KEY_DIM + ch] = y * rsqrtf(tot + EPS_) * scale;
}

// ---------------- conv + silu for v ---------------------------------------
__global__ __launch_bounds__(256) void convv_kernel(
    const float* __restrict__ pre, const float* __restrict__ cw,
    float* __restrict__ out)
{
    int idx = blockIdx.x * blockDim.x + threadIdx.x;
    int t = idx >> 11;
    int ch = idx & 2047;
    float y = 0.f;
#pragma unroll
    for (int j = 0; j < CONV; j++) {
        int tt = t - (CONV-1) + j;
        float xv = (tt >= 0) ? pre[(size_t)tt * VAL_DIM + ch] : 0.f;
        y = fmaf(xv, cw[ch*CONV + j], y);
    }
    out[idx] = y / (1.f + expf(-y));
}

// ---------------- C[t][hk] = k_{t+1} . k_t per key head --------------------
__global__ __launch_bounds__(256) void dotck_kernel(
    const float* __restrict__ k, float* __restrict__ Cq)
{
    int warp = threadIdx.x >> 5;
    int lane = threadIdx.x & 31;
    int idx = blockIdx.x * 8 + warp;       // t*NH + hk
    int t = idx >> 3, hk = idx & 7;
    float cv = 0.f;
    if (t + 1 < S_LEN) {
        const float* k0 = k + (size_t)t * KEY_DIM + hk * DK + lane * 4;
        const float* k1 = k0 + KEY_DIM;
        float4 a = *(const float4*)k0;
        float4 b = *(const float4*)k1;
        cv = a.x*b.x + a.y*b.y + a.z*b.z + a.w*b.w;
#pragma unroll
        for (int off = 16; off; off >>= 1) cv += __shfl_xor_sync(0xffffffffu, cv, off);
    }
    if (lane == 0) Cq[(size_t)t * NH + hk] = cv;
}

// ---------------- delta-rule scan v3 (scalarized serial chain) -------------
// P1_t = k_t.S_{t-1}; A_t = k_{t+1}.S_{t-1} (slack-reduced);
// delta = (v - d*P1)*beta; S = d*S + k*delta; o_t = q_t.S_t (lazy reduce);
// P1_{t+1} = d*A_t + C_t*delta  with C_t = k_{t+1}.k_t precomputed.
#define CH 16

__global__ __launch_bounds__(128) void scan_kernel(
    const float* __restrict__ k, const float* __restrict__ q,
    const float* __restrict__ v, const float2* __restrict__ db,
    const float* __restrict__ Cq, float* __restrict__ o)
{
    __shared__ float ks[2][CH + 1][DK];
    __shared__ float qs[2][CH][DK];
    __shared__ float vs[2][CH][16];
    __shared__ float2 dbs[2][CH];
    __shared__ float cs[2][CH];

    int h = blockIdx.x >> 3;
    int hk = h >> 1;
    int colbase = (blockIdx.x & 7) * 16;
    int tid = threadIdx.x;
    int w = tid >> 5, lane = tid & 31;
    int g = lane >> 3, s = lane & 7;
    int col = colbase + w * 4 + g;

    int lr = tid >> 3;            // 0..15
    int lo = (tid & 7) * 16;
    int vr = tid >> 2;            // 0..31 (tid<64)

    const float* kbase = k + hk * DK;
    const float* qbase = q + hk * DK;
    const float* vbase = v + h * DV + colbase + (tid & 3) * 4;
    const float2* dbase = db + h;
    const float* cbase = Cq + hk;
    float* obase = o + h * DV + col;

    // ---- issue chunk 0 (rows 0..CH incl overlap row) ----
    {
#pragma unroll
        for (int j = 0; j < 4; j++) {
            cp16(&ks[0][lr][lo + j*4], kbase + (size_t)lr * KEY_DIM + lo + j*4);
            cp16(&qs[0][lr][lo + j*4], qbase + (size_t)lr * KEY_DIM + lo + j*4);
        }
        if (tid < 8) {
#pragma unroll
            for (int j = 0; j < 4; j++)
                cp16(&ks[0][CH][tid*16 + j*4], kbase + (size_t)CH * KEY_DIM + tid*16 + j*4);
        }
        if (tid < 64) cp16(&vs[0][vr][(tid & 3) * 4], vbase + (size_t)vr * VAL_DIM);
        if (tid < CH) cp8(&dbs[0][tid], dbase + (size_t)tid * NVH);
        if (tid < CH) cp4(&cs[0][tid], cbase + (size_t)tid * NH);
        cp_commit();
    }

    float S[16];
#pragma unroll
    for (int i = 0; i < 16; i++) S[i] = 0.f;
    float P1 = 0.f;
    float kc[16];
    bool kc_init = false;

    int buf = 0;
    const int NCH = S_LEN / CH;
    for (int c = 0; c < NCH; c++) {
        if (c + 1 < NCH) {
            int t0 = (c + 1) * CH;
            int p = buf ^ 1;
#pragma unroll
            for (int j = 0; j < 4; j++) {
                cp16(&ks[p][lr][lo + j*4], kbase + (size_t)(t0 + lr) * KEY_DIM + lo + j*4);
                cp16(&qs[p][lr][lo + j*4], qbase + (size_t)(t0 + lr) * KEY_DIM + lo + j*4);
            }
            if (tid < 8) {
                int ovr = t0 + CH; if (ovr > S_LEN - 1) ovr = S_LEN - 1;
#pragma unroll
                for (int j = 0; j < 4; j++)
                    cp16(&ks[p][CH][tid*16 + j*4], kbase + (size_t)ovr * KEY_DIM + tid*16 + j*4);
            }
            if (tid < 64) cp16(&vs[p][vr][(tid & 3) * 4], vbase + (size_t)(t0 + vr) * VAL_DIM);
            if (tid < CH) cp8(&dbs[p][tid], dbase + (size_t)(t0 + tid) * NVH);
            if (tid < CH) cp4(&cs[p][tid], cbase + (size_t)(t0 + tid) * NH);
            cp_commit();
            asm volatile("cp.async.wait_group 1;");
        } else {
            asm volatile("cp.async.wait_group 0;");
        }
        __syncthreads();

        if (!kc_init) {   // first chunk: load k_0
#pragma unroll
            for (int i = 0; i < 16; i += 4)
                *(float4*)&kc[i] = *(const float4*)&ks[0][0][s * 16 + i];
            kc_init = true;
        }

        int t0 = c * CH;
        float* ob = obase + (size_t)t0 * VAL_DIM;
#pragma unroll
        for (int tt = 0; tt < CH; tt++) {
            // load k_{t+1}, q_t
            float kn[16], qc[16];
#pragma unroll
            for (int i = 0; i < 16; i += 4) {
                *(float4*)&kn[i] = *(const float4*)&ks[buf][tt + 1][s * 16 + i];
                *(float4*)&qc[i] = *(const float4*)&qs[buf][tt][s * 16 + i];
            }
            float vc = vs[buf][tt][w * 4 + g];
            float2 dc = dbs[buf][tt];
            float Ct = cs[buf][tt];

            // A = k_{t+1} . S_{t-1}   (independent of delta)
            float a0 = 0.f, a1 = 0.f, a2 = 0.f, a3 = 0.f;
#pragma unroll
            for (int i = 0; i < 16; i += 4) {
                a0 = fmaf(kn[i],   S[i],   a0);
                a1 = fmaf(kn[i+1], S[i+1], a1);
                a2 = fmaf(kn[i+2], S[i+2], a2);
                a3 = fmaf(kn[i+3], S[i+3], a3);
            }
            float A = (a0 + a1) + (a2 + a3);

            // scalar chain
            float delta = (vc - dc.x * P1) * dc.y;

            // S update + o-dot
            float b0 = 0.f, b1 = 0.f, b2 = 0.f, b3 = 0.f;
#pragma unroll
            for (int i = 0; i < 16; i += 4) {
                S[i]   = fmaf(S[i],   dc.x, kc[i]   * delta);
                S[i+1] = fmaf(S[i+1], dc.x, kc[i+1] * delta);
                S[i+2] = fmaf(S[i+2], dc.x, kc[i+2] * delta);
                S[i+3] = fmaf(S[i+3], dc.x, kc[i+3] * delta);
                b0 = fmaf(qc[i],   S[i],   b0);
                b1 = fmaf(qc[i+1], S[i+1], b1);
                b2 = fmaf(qc[i+2], S[i+2], b2);
                b3 = fmaf(qc[i+3], S[i+3], b3);
            }
            float ov = (b0 + b1) + (b2 + b3);

            // reductions (off the serial chain)
            A  += __shfl_xor_sync(0xffffffffu, A, 1);
            A  += __shfl_xor_sync(0xffffffffu, A, 2);
            A  += __shfl_xor_sync(0xffffffffu, A, 4);
            ov += __shfl_xor_sync(0xffffffffu, ov, 1);
            ov += __shfl_xor_sync(0xffffffffu, ov, 2);
            ov += __shfl_xor_sync(0xffffffffu, ov, 4);
            if (s == 0) ob[(size_t)tt * VAL_DIM] = ov;

            P1 = fmaf(dc.x, A, Ct * delta);
#pragma unroll
            for (int i = 0; i < 16; i++) kc[i] = kn[i];
        }
        __syncthreads();
        buf ^= 1;
    }
}

// ---------------- gated RMS norm ------------------------------------------
__global__ __launch_bounds__(128) void gnorm_kernel(
    const float* __restrict__ o, const float* __restrict__ gate,
    const float* __restrict__ w_norm, float* __restrict__ og)
{
    int t = blockIdx.x >> 4;
    int h = blockIdx.x & 15;
    int c = threadIdx.x;
    size_t idx = (size_t)t * VAL_DIM + h * DV + c;
    float gt = gate[idx];
    float y = o[idx] * (gt / (1.f + expf(-gt)));
    float ss = y * y;
#pragma unroll
    for (int off = 16; off; off >>= 1) ss += __shfl_xor_sync(0xffffffffu, ss, off);
    __shared__ float wss[4];
    if ((threadIdx.x & 31) == 0) wss[threadIdx.x >> 5] = ss;
    __syncthreads();
    float mean = (wss[0] + wss[1] + wss[2] + wss[3]) * (1.f / DV);
    og[idx] = y * rsqrtf(mean + EPS_) * w_norm[c];
}

// ---------------- launch ---------------------------------------------------
extern "C" void kernel_launch(void* const* d_in, const int* in_sizes, int n_in,
                              void* d_out, int out_size)
{
    const float* x      = (const float*)d_in[0];
    const float* Wq     = (const float*)d_in[1];
    const float* Wk     = (const float*)d_in[2];
    const float* Wv     = (const float*)d_in[3];
    const float* Wa     = (const float*)d_in[4];
    const float* Wb     = (const float*)d_in[5];
    const float* Wg     = (const float*)d_in[6];
    const float* Wo     = (const float*)d_in[7];
    const float* conv_q = (const float*)d_in[8];
    const float* conv_k = (const float*)d_in[9];
    const float* conv_v = (const float*)d_in[10];
    const float* A_log  = (const float*)d_in[11];
    const float* dt_b   = (const float*)d_in[12];
    const float* w_norm = (const float*)d_in[13];

    void* wsp = nullptr;
    cudaGetSymbolAddress(&wsp, g_ws_gdn);
    float* ws = (float*)wsp;
    float* qpre = ws + OF_QPRE;
    float* kpre = ws + OF_KPRE;
    float* vpre = ws + OF_VPRE;
    float* gate = ws + OF_GATE;
    float* qn   = ws + OF_QN;
    float* kn   = ws + OF_KN;
    float* vn   = ws + OF_VN;
    float2* db  = (float2*)(ws + OF_DB);
    float* Cq   = ws + OF_CQ;
    float* o    = ws + OF_O;
    float* og   = ws + OF_OG;
    float* out  = (float*)d_out;

    dim3 blk(256);
    dim3 g_x4(48, S_LEN / GBM);              // merged Wq/Wk/Wv/Wg
    dim3 g_o (VAL_DIM / GBN, S_LEN / GBM);   // Wo: (16,32)

    gemm_x4<<<g_x4, blk>>>(x, Wq, Wk, Wv, Wg, qpre, kpre, vpre, gate);
    gemv_ab<<<S_LEN / 8, 128>>>(x, Wa, Wb, A_log, dt_b, db);

    convqk_kernel<<<S_LEN * NH, 128>>>(qpre, conv_q, qn, SCALE_);
    convqk_kernel<<<S_LEN * NH, 128>>>(kpre, conv_k, kn, 1.f);
    convv_kernel<<<(S_LEN * VAL_DIM) / 256, 256>>>(vpre, conv_v, vn);
    dotck_kernel<<<S_LEN * NH / 8, 256>>>(kn, Cq);

    scan_kernel<<<128, 128>>>(kn, qn, vn, db, Cq, o);

    gnorm_kernel<<<S_LEN * NVH, 128>>>(o, gate, w_norm, og);

    gemm_tf32<<<g_o, blk>>>(og, Wo, out, HID, VAL_DIM);
}